// round 9
// baseline (speedup 1.0000x reference)
#include <cuda_runtime.h>
#include <cuda_bf16.h>
#include <math.h>

// ---------------------------------------------------------------------------
// MPNN on GB300 (round 9).
//  - GEMM blocks: 256 threads, 128 nodes, 4 rows x 8 cols per thread.
//    Same 100KB smem (2 blocks/SM) but 16 warps/SM -> 4 warps/SMSP,
//    doubling latency coverage (round-8 profile: occ 10.6%, issue 20.8%).
//  - Padded-slot adjacency, fused layer (GEMM1+GEMM2), fused readout.
// ---------------------------------------------------------------------------

#define MAXN 65536
#define MAXG 512
#define FD   64
#define SLOT 96

typedef unsigned long long ull;

__device__ int   g_deg[MAXN];
__device__ int   g_srcpad[MAXN * SLOT];
__device__ int   g_degmax;

__device__ float g_h[MAXN * FD];
__device__ float g_nagg[MAXN * FD];
__device__ float g_naggH[MAXN * FD];
__device__ float g_eemb[MAXN * FD];
__device__ float g_curA[MAXN * FD];
__device__ float g_curB[MAXN * FD];

__device__ float g_means[MAXG * FD];
__device__ float g_cnt[MAXG];
__device__ float g_gconst[MAXG];

// ---------------------------------------------------------------------------
// One pass: edges -> padded slots (threads [0,E)) + node init (threads >= E)
__global__ void k_fillpad(const int* __restrict__ row, const int* __restrict__ col,
                          const float* __restrict__ x, const float* __restrict__ Wi,
                          const float* __restrict__ We1, int E, int n, int nobs) {
    int i = blockIdx.x * blockDim.x + threadIdx.x;
    if (i < E) {
        int c = col[i];
        int p = atomicAdd(&g_deg[c], 1);
        if (p < SLOT) g_srcpad[c * SLOT + p] = row[i];
    } else {
        int t = i - E;
        if (t >= n * 64) return;
        int node = t >> 6, c = t & 63;
        const float* xr = x + node * nobs;
        float s1 = 0.f, s2 = 0.f;
        for (int j = 0; j < nobs; j++) {
            float xv = __ldg(&xr[j]);
            s1 += xv * __ldg(&Wi[j * 64 + c]);
            if (c < 63) s2 += xv * __ldg(&We1[j * 63 + c]);
        }
        g_curA[t] = fmaxf(s1, 0.f);
        g_h[t]    = (c < 63) ? fmaxf(s2, 0.f) : 0.f;
    }
}

// fused double gather over padded slots + block degmax -> g_degmax
__global__ void k_dgather(const float* __restrict__ h, const float* __restrict__ cur,
                          float* __restrict__ outH, float* __restrict__ outC, int n) {
    __shared__ int ssmax;
    int tid = threadIdx.x;
    if (tid == 0) ssmax = 0;
    __syncthreads();

    int hw = (blockIdx.x * blockDim.x + tid) >> 4;
    int lane = tid & 15;
    bool valid = (hw < n);
    int d = valid ? g_deg[hw] : 0;
    int dc = min(d, SLOT);
    int base = hw * SLOT;
    const float4* h4 = (const float4*)h;
    const float4* c4 = (const float4*)cur;
    float hx = 0.f, hy = 0.f, hz = 0.f, hw_ = 0.f;
    float cx = 0.f, cy = 0.f, cz = 0.f, cw = 0.f;
    int i = 0;
    for (; i + 4 <= dc; i += 4) {
        int s0 = __ldg(&g_srcpad[base + i]);
        int s1 = __ldg(&g_srcpad[base + i + 1]);
        int s2 = __ldg(&g_srcpad[base + i + 2]);
        int s3 = __ldg(&g_srcpad[base + i + 3]);
        float4 a0 = __ldg(&h4[s0 * 16 + lane]);
        float4 a1 = __ldg(&h4[s1 * 16 + lane]);
        float4 a2 = __ldg(&h4[s2 * 16 + lane]);
        float4 a3 = __ldg(&h4[s3 * 16 + lane]);
        float4 b0 = __ldg(&c4[s0 * 16 + lane]);
        float4 b1 = __ldg(&c4[s1 * 16 + lane]);
        float4 b2 = __ldg(&c4[s2 * 16 + lane]);
        float4 b3 = __ldg(&c4[s3 * 16 + lane]);
        hx += (a0.x + a1.x) + (a2.x + a3.x);
        hy += (a0.y + a1.y) + (a2.y + a3.y);
        hz += (a0.z + a1.z) + (a2.z + a3.z);
        hw_ += (a0.w + a1.w) + (a2.w + a3.w);
        cx += (b0.x + b1.x) + (b2.x + b3.x);
        cy += (b0.y + b1.y) + (b2.y + b3.y);
        cz += (b0.z + b1.z) + (b2.z + b3.z);
        cw += (b0.w + b1.w) + (b2.w + b3.w);
    }
    for (; i < dc; i++) {
        int s = __ldg(&g_srcpad[base + i]);
        float4 a = __ldg(&h4[s * 16 + lane]);
        float4 b = __ldg(&c4[s * 16 + lane]);
        hx += a.x; hy += a.y; hz += a.z; hw_ += a.w;
        cx += b.x; cy += b.y; cz += b.z; cw += b.w;
    }
    if (valid) {
        float sc = (d > 0) ? (1.0f / (float)d) : 0.0f;
        hx *= sc; hy *= sc; hz *= sc; hw_ *= sc;
        cx *= sc; cy *= sc; cz *= sc; cw *= sc;
        if (lane == 15) hw_ = 0.f;   // patched to deg/degmax in k_gemm64 staging
        ((float4*)outH)[hw * 16 + lane] = make_float4(hx, hy, hz, hw_);
        ((float4*)outC)[hw * 16 + lane] = make_float4(cx, cy, cz, cw);
    }
    if (lane == 0 && valid) atomicMax(&ssmax, d);
    __syncthreads();
    if (tid == 0) atomicMax(&g_degmax, ssmax);
}

// single gather over padded slots
__global__ void k_gather(const float* __restrict__ feat, float* __restrict__ out, int n) {
    int hw = (blockIdx.x * blockDim.x + threadIdx.x) >> 4;
    int lane = threadIdx.x & 15;
    if (hw >= n) return;
    int d = g_deg[hw];
    int dc = min(d, SLOT);
    int base = hw * SLOT;
    const float4* f4 = (const float4*)feat;
    float ax = 0.f, ay = 0.f, az = 0.f, aw = 0.f;
    int i = 0;
    for (; i + 4 <= dc; i += 4) {
        int s0 = __ldg(&g_srcpad[base + i]);
        int s1 = __ldg(&g_srcpad[base + i + 1]);
        int s2 = __ldg(&g_srcpad[base + i + 2]);
        int s3 = __ldg(&g_srcpad[base + i + 3]);
        float4 v0 = __ldg(&f4[s0 * 16 + lane]);
        float4 v1 = __ldg(&f4[s1 * 16 + lane]);
        float4 v2 = __ldg(&f4[s2 * 16 + lane]);
        float4 v3 = __ldg(&f4[s3 * 16 + lane]);
        ax += (v0.x + v1.x) + (v2.x + v3.x);
        ay += (v0.y + v1.y) + (v2.y + v3.y);
        az += (v0.z + v1.z) + (v2.z + v3.z);
        aw += (v0.w + v1.w) + (v2.w + v3.w);
    }
    for (; i < dc; i++) {
        int s = __ldg(&g_srcpad[base + i]);
        float4 v = __ldg(&f4[s * 16 + lane]);
        ax += v.x; ay += v.y; az += v.z; aw += v.w;
    }
    float sc = (d > 0) ? (1.0f / (float)d) : 0.0f;
    ((float4*)out)[hw * 16 + lane] = make_float4(ax * sc, ay * sc, az * sc, aw * sc);
}

// ---------------------------------------------------------------------------
// GEMM core, 4 rows x 8 cols per thread (256 threads, 128 nodes).
// q = tid&7 (col group q*8), rr = tid>>3 (0..31), rows rr + 32j, j=0..3.
template <int K, int PITCH>
__device__ __forceinline__ void gemm_core4x8(const float* __restrict__ ins,
                                             const float* __restrict__ Ws,
                                             ull acc[4][4]) {
    int q  = threadIdx.x & 7;
    int rr = threadIdx.x >> 3;
#pragma unroll
    for (int j = 0; j < 4; j++)
#pragma unroll
        for (int m = 0; m < 4; m++) acc[j][m] = 0ull;

#pragma unroll 2
    for (int k = 0; k < K; k += 4) {
        float4 a[4];
#pragma unroll
        for (int j = 0; j < 4; j++)
            a[j] = *(const float4*)&ins[(rr + 32 * j) * PITCH + k];
#pragma unroll
        for (int kk = 0; kk < 4; kk++) {
            ulonglong2 w = *(const ulonglong2*)&Ws[(k + kk) * 64 + q * 8];
            ulonglong2 w2 = *(const ulonglong2*)&Ws[(k + kk) * 64 + q * 8 + 4];
#pragma unroll
            for (int j = 0; j < 4; j++) {
                float av = (kk == 0) ? a[j].x : (kk == 1) ? a[j].y
                         : (kk == 2) ? a[j].z : a[j].w;
                ull p;
                asm("mov.b64 %0, {%1, %1};" : "=l"(p) : "f"(av));
                asm("fma.rn.f32x2 %0, %1, %2, %0;" : "+l"(acc[j][0]) : "l"(p), "l"(w.x));
                asm("fma.rn.f32x2 %0, %1, %2, %0;" : "+l"(acc[j][1]) : "l"(p), "l"(w.y));
                asm("fma.rn.f32x2 %0, %1, %2, %0;" : "+l"(acc[j][2]) : "l"(p), "l"(w2.x));
                asm("fma.rn.f32x2 %0, %1, %2, %0;" : "+l"(acc[j][3]) : "l"(p), "l"(w2.y));
            }
        }
    }
}

__device__ __forceinline__ float4 acc_relu4(ull a0, ull a1) {
    float lo0, hi0, lo1, hi1;
    asm("mov.b64 {%0, %1}, %2;" : "=f"(lo0), "=f"(hi0) : "l"(a0));
    asm("mov.b64 {%0, %1}, %2;" : "=f"(lo1), "=f"(hi1) : "l"(a1));
    float4 o;
    o.x = fmaxf(lo0, 0.f); o.y = fmaxf(hi0, 0.f);
    o.z = fmaxf(lo1, 0.f); o.w = fmaxf(hi1, 0.f);
    return o;
}

// Fused layer: msg = relu(concat(nagg, eemb) @ Wmsg);
//              cout = relu(concat(cur, msg) @ Wupd).  LAST fuses the readout.
template <bool LAST>
__global__ __launch_bounds__(256) void k_layer2(const float* __restrict__ nagg,
                                                const float* __restrict__ eemb,
                                                const float* __restrict__ cur,
                                                const float* __restrict__ Wmsg,
                                                const float* __restrict__ Wupd,
                                                float* __restrict__ cout,
                                                const float* __restrict__ Wr,
                                                const int* __restrict__ batch,
                                                float* __restrict__ out, int n) {
    extern __shared__ float sm[];
    const int PITCH = 132;
    float* Ws  = sm;                 // 128*64
    float* ins = sm + 128 * 64;      // 128*PITCH
    __shared__ float Wrs[64];
    int tid = threadIdx.x;
    int node0 = blockIdx.x * 128;
    int q  = tid & 7;
    int rr = tid >> 3;

    for (int idx = tid; idx < 128 * 16; idx += 256)
        ((float4*)Ws)[idx] = __ldg((const float4*)Wmsg + idx);
    if (LAST && tid < 64) Wrs[tid] = __ldg(&Wr[64 + tid]);
    for (int idx = tid; idx < 2048; idx += 256) {
        int r = idx >> 4, c4 = (idx & 15) << 2;
        int node = node0 + r;
        float4 va = make_float4(0.f, 0.f, 0.f, 0.f), vb = va;
        if (node < n) {
            va = __ldg((const float4*)&nagg[(size_t)node * 64 + c4]);
            vb = __ldg((const float4*)&eemb[(size_t)node * 64 + c4]);
        }
        *(float4*)&ins[r * PITCH + c4]      = va;
        *(float4*)&ins[r * PITCH + 64 + c4] = vb;
    }
    __syncthreads();

    ull acc[4][4];
    gemm_core4x8<128, PITCH>(ins, Ws, acc);
    float4 o[4][2];
#pragma unroll
    for (int j = 0; j < 4; j++) {
        o[j][0] = acc_relu4(acc[j][0], acc[j][1]);
        o[j][1] = acc_relu4(acc[j][2], acc[j][3]);
    }
    __syncthreads();

#pragma unroll
    for (int j = 0; j < 4; j++) {
        float* dst = &ins[(rr + 32 * j) * PITCH + 64 + q * 8];
        *(float4*)&dst[0] = o[j][0];
        *(float4*)&dst[4] = o[j][1];
    }
    for (int idx = tid; idx < 2048; idx += 256) {
        int r = idx >> 4, c4 = (idx & 15) << 2;
        int node = node0 + r;
        float4 vc = (node < n) ? __ldg((const float4*)&cur[(size_t)node * 64 + c4])
                               : make_float4(0.f, 0.f, 0.f, 0.f);
        *(float4*)&ins[r * PITCH + c4] = vc;
    }
    for (int idx = tid; idx < 128 * 16; idx += 256)
        ((float4*)Ws)[idx] = __ldg((const float4*)Wupd + idx);
    __syncthreads();

    gemm_core4x8<128, PITCH>(ins, Ws, acc);
#pragma unroll
    for (int j = 0; j < 4; j++) {
        o[j][0] = acc_relu4(acc[j][0], acc[j][1]);
        o[j][1] = acc_relu4(acc[j][2], acc[j][3]);
    }

    if (!LAST) {
#pragma unroll
        for (int j = 0; j < 4; j++) {
            int node = node0 + rr + 32 * j;
            if (node < n) {
                float* Cr = &cout[(size_t)node * 64 + q * 8];
                *(float4*)&Cr[0] = o[j][0];
                *(float4*)&Cr[4] = o[j][1];
            }
        }
    } else {
        const float* wv = &Wrs[q * 8];
        float4 w0 = *(const float4*)&wv[0];
        float4 w1 = *(const float4*)&wv[4];
#pragma unroll
        for (int j = 0; j < 4; j++) {
            float dv = o[j][0].x * w0.x + o[j][0].y * w0.y + o[j][0].z * w0.z + o[j][0].w * w0.w
                     + o[j][1].x * w1.x + o[j][1].y * w1.y + o[j][1].z * w1.z + o[j][1].w * w1.w;
            dv += __shfl_xor_sync(0xffffffffu, dv, 1);
            dv += __shfl_xor_sync(0xffffffffu, dv, 2);
            dv += __shfl_xor_sync(0xffffffffu, dv, 4);
            int node = node0 + rr + 32 * j;
            if (q == 0 && node < n) out[node] = dv;
        }
        __syncthreads();
#pragma unroll
        for (int j = 0; j < 4; j++) {
            float* dst = &ins[(rr + 32 * j) * PITCH + q * 8];
            *(float4*)&dst[0] = o[j][0];
            *(float4*)&dst[4] = o[j][1];
        }
        __syncthreads();
        if (tid < 64) {
            int c = tid;
            float acc2 = 0.f, cnt = 0.f;
            int curb = -1;
            for (int i = 0; i < 128; i++) {
                int node = node0 + i;
                if (node >= n) break;
                int b = __ldg(&batch[node]);
                if (b != curb) {
                    if (curb >= 0) {
                        atomicAdd(&g_means[curb * 64 + c], acc2);
                        if (c == 0) atomicAdd(&g_cnt[curb], cnt);
                    }
                    acc2 = 0.f; cnt = 0.f; curb = b;
                }
                acc2 += ins[i * PITCH + c];
                cnt += 1.f;
            }
            if (curb >= 0) {
                atomicAdd(&g_means[curb * 64 + c], acc2);
                if (c == 0) atomicAdd(&g_cnt[curb], cnt);
            }
        }
    }
}

// eemb = relu( naggH @ We2 ), K=64; staging patches col 63 = deg/degmax
__global__ __launch_bounds__(256) void k_gemm64(const float* __restrict__ A,
                                                const float* __restrict__ W,
                                                float* __restrict__ C, int n) {
    extern __shared__ float sm[];
    const int PITCH = 68;
    float* Ws  = sm;               // 64*64
    float* ins = sm + 64 * 64;     // 128*68
    int tid = threadIdx.x;
    int node0 = blockIdx.x * 128;
    float dmx = (float)max(g_degmax, 1);

    for (int idx = tid; idx < 64 * 16; idx += 256)
        ((float4*)Ws)[idx] = __ldg((const float4*)W + idx);
    for (int idx = tid; idx < 2048; idx += 256) {
        int r = idx >> 4, c4 = (idx & 15) << 2;
        int node = node0 + r;
        float4 va = make_float4(0.f, 0.f, 0.f, 0.f);
        if (node < n) {
            va = __ldg((const float4*)&A[(size_t)node * 64 + c4]);
            if (c4 == 60) va.w = (float)g_deg[node] / dmx;
        }
        *(float4*)&ins[r * PITCH + c4] = va;
    }
    __syncthreads();

    ull acc[4][4];
    gemm_core4x8<64, PITCH>(ins, Ws, acc);

    int q  = tid & 7;
    int rr = tid >> 3;
#pragma unroll
    for (int j = 0; j < 4; j++) {
        int node = node0 + rr + 32 * j;
        if (node < n) {
            float* Cr = &C[(size_t)node * 64 + q * 8];
            *(float4*)&Cr[0] = acc_relu4(acc[j][0], acc[j][1]);
            *(float4*)&Cr[4] = acc_relu4(acc[j][2], acc[j][3]);
        }
    }
}

// gconst[g] = relu(mean_g @ W_pool) . W_read[:64] + b_read
__global__ void k_gconst(const float* __restrict__ Wp, const float* __restrict__ Wr,
                         const float* __restrict__ br) {
    int g = blockIdx.x;
    int t = threadIdx.x;
    __shared__ float m[64];
    __shared__ float red[64];
    float cnt = g_cnt[g];
    if (cnt <= 0.f) { if (t == 0) g_gconst[g] = 0.f; return; }
    m[t] = g_means[g * 64 + t] / cnt;
    __syncthreads();
    float p = 0.f;
#pragma unroll 8
    for (int k = 0; k < 64; k++) p += m[k] * __ldg(&Wp[k * 64 + t]);
    red[t] = fmaxf(p, 0.f) * __ldg(&Wr[t]);
    __syncthreads();
    if (t < 32) {
        float s = red[t] + red[t + 32];
#pragma unroll
        for (int off = 16; off > 0; off >>= 1) s += __shfl_down_sync(0xffffffffu, s, off);
        if (t == 0) g_gconst[g] = s + __ldg(&br[0]);
    }
}

// out[i] += gconst[batch[i]]
__global__ void k_addg(const int* __restrict__ batch, float* __restrict__ out, int n) {
    int i = blockIdx.x * blockDim.x + threadIdx.x;
    if (i < n) out[i] += g_gconst[__ldg(&batch[i])];
}

// ---------------------------------------------------------------------------
extern "C" void kernel_launch(void* const* d_in, const int* in_sizes, int n_in,
                              void* d_out, int out_size) {
    const float* x    = (const float*)d_in[0];
    const float* Wi   = (const float*)d_in[1];
    const float* We1  = (const float*)d_in[2];
    const float* We2  = (const float*)d_in[3];
    const float* Wmsg = (const float*)d_in[4];
    const float* Wupd = (const float*)d_in[5];
    const float* Wp   = (const float*)d_in[6];
    const float* Wr   = (const float*)d_in[7];
    const float* br   = (const float*)d_in[8];
    const int*   eidx = (const int*)d_in[9];
    const int*   batch= (const int*)d_in[10];

    int n    = in_sizes[10];
    int E    = in_sizes[9] / 2;
    int nobs = in_sizes[0] / n;
    int L    = in_sizes[4] / (128 * 64);
    const int* row = eidx;
    const int* col = eidx + E;
    float* out = (float*)d_out;

    float *curA, *curB, *hbuf, *nagg, *naggH, *eemb, *means, *cnt;
    int *deg, *degmax;
    cudaGetSymbolAddress((void**)&curA, g_curA);
    cudaGetSymbolAddress((void**)&curB, g_curB);
    cudaGetSymbolAddress((void**)&hbuf, g_h);
    cudaGetSymbolAddress((void**)&nagg, g_nagg);
    cudaGetSymbolAddress((void**)&naggH, g_naggH);
    cudaGetSymbolAddress((void**)&eemb, g_eemb);
    cudaGetSymbolAddress((void**)&means, g_means);
    cudaGetSymbolAddress((void**)&cnt,   g_cnt);
    cudaGetSymbolAddress((void**)&deg,   g_deg);
    cudaGetSymbolAddress((void**)&degmax, g_degmax);

    const int SMEM128 = (128 * 64 + 128 * 132) * 4;  // 100352
    const int SMEM64  = (64 * 64 + 128 * 68) * 4;    // 51200
    cudaFuncSetAttribute(k_layer2<false>, cudaFuncAttributeMaxDynamicSharedMemorySize, SMEM128);
    cudaFuncSetAttribute(k_layer2<true>,  cudaFuncAttributeMaxDynamicSharedMemorySize, SMEM128);
    cudaFuncSetAttribute(k_gemm64, cudaFuncAttributeMaxDynamicSharedMemorySize, SMEM64);

    int gFI = (E + n * 64 + 255) / 256;
    int gHW = (n * 16 + 255) / 256;
    int gG  = (n + 127) / 128;
    int gA  = (n + 255) / 256;

    cudaMemsetAsync(deg,    0, (size_t)n * sizeof(int));
    cudaMemsetAsync(degmax, 0, sizeof(int));
    cudaMemsetAsync(means,  0, (size_t)MAXG * FD * sizeof(float));
    cudaMemsetAsync(cnt,    0, (size_t)MAXG * sizeof(float));

    k_fillpad<<<gFI, 256>>>(row, col, x, Wi, We1, E, n, nobs);   // kernel 1
    k_dgather<<<gHW, 256>>>(hbuf, curA, naggH, nagg, n);         // kernel 2
    k_gemm64<<<gG, 256, SMEM64>>>(naggH, We2, eemb, n);          // kernel 3

    float* cin = curA;
    float* cout = curB;
    for (int l = 0; l < L; l++) {
        bool last = (l == L - 1);
        if (l > 0) k_gather<<<gHW, 256>>>(cin, nagg, n);
        if (!last) {
            k_layer2<false><<<gG, 256, SMEM128>>>(nagg, eemb, cin,        // kernel 4 (l=0): profiled
                                                  Wmsg + (size_t)l * 8192,
                                                  Wupd + (size_t)l * 8192,
                                                  cout, nullptr, nullptr, nullptr, n);
            float* tmp = cin; cin = cout; cout = tmp;
        } else {
            k_layer2<true><<<gG, 256, SMEM128>>>(nagg, eemb, cin,
                                                 Wmsg + (size_t)l * 8192,
                                                 Wupd + (size_t)l * 8192,
                                                 nullptr, Wr, batch, out, n);
        }
    }

    k_gconst<<<MAXG, 64>>>(Wp, Wr, br);
    k_addg<<<gA, 256>>>(batch, out, n);
}

// round 12
// speedup vs baseline: 1.7536x; 1.7536x over previous
#include <cuda_runtime.h>
#include <cuda_bf16.h>
#include <cstdint>
#include <math.h>

// ---------------------------------------------------------------------------
// MPNN on GB300 (round 12).
//  - tcgen05 is sm_103a-only and the harness targets compute_103 -> blocked.
//    Layer GEMMs now use mma.sync.m16n8k8 tf32 (base ISA, HMMA on tensor pipe).
//  - Per block: 128 nodes, 256 thr (8 warps x 16 rows). A frags direct from
//    global (exclusive ownership), B staged fragment-major in smem (pad-20),
//    msg exchanged via pitch-68 smem. Fused 2-GEMM layer + fused readout.
//  - Everything else identical to the round-8 352us kernel set.
// ---------------------------------------------------------------------------

#define MAXN 65536
#define MAXG 512
#define FD   64
#define SLOT 96

typedef unsigned long long ull;

__device__ int   g_deg[MAXN];
__device__ int   g_srcpad[MAXN * SLOT];
__device__ int   g_degmax;

__device__ float g_h[MAXN * FD];
__device__ float g_nagg[MAXN * FD];
__device__ float g_naggH[MAXN * FD];
__device__ float g_eemb[MAXN * FD];
__device__ float g_curA[MAXN * FD];
__device__ float g_curB[MAXN * FD];

__device__ float g_means[MAXG * FD];
__device__ float g_cnt[MAXG];
__device__ float g_gconst[MAXG];

// ----------------------------- helpers ------------------------------------
__device__ __forceinline__ uint32_t tf32r(float x) {
    uint32_t y;
    asm("cvt.rna.tf32.f32 %0, %1;" : "=r"(y) : "f"(x));
    return y;
}

__device__ __forceinline__ void mma_tf32(float acc[4], uint32_t a0, uint32_t a1,
                                         uint32_t a2, uint32_t a3,
                                         uint32_t b0, uint32_t b1) {
    asm volatile("mma.sync.aligned.m16n8k8.row.col.f32.tf32.tf32.f32 "
                 "{%0,%1,%2,%3}, {%4,%5,%6,%7}, {%8,%9}, {%0,%1,%2,%3};"
                 : "+f"(acc[0]), "+f"(acc[1]), "+f"(acc[2]), "+f"(acc[3])
                 : "r"(a0), "r"(a1), "r"(a2), "r"(a3), "r"(b0), "r"(b1));
}

// ----------------------------- structure build -----------------------------
__global__ void k_fillpad(const int* __restrict__ row, const int* __restrict__ col,
                          const float* __restrict__ x, const float* __restrict__ Wi,
                          const float* __restrict__ We1, int E, int n, int nobs) {
    int i = blockIdx.x * blockDim.x + threadIdx.x;
    if (i < E) {
        int c = col[i];
        int p = atomicAdd(&g_deg[c], 1);
        if (p < SLOT) g_srcpad[c * SLOT + p] = row[i];
    } else {
        int t = i - E;
        if (t >= n * 64) return;
        int node = t >> 6, c = t & 63;
        const float* xr = x + node * nobs;
        float s1 = 0.f, s2 = 0.f;
        for (int j = 0; j < nobs; j++) {
            float xv = __ldg(&xr[j]);
            s1 += xv * __ldg(&Wi[j * 64 + c]);
            if (c < 63) s2 += xv * __ldg(&We1[j * 63 + c]);
        }
        g_curA[t] = fmaxf(s1, 0.f);
        g_h[t]    = (c < 63) ? fmaxf(s2, 0.f) : 0.f;
    }
}

__global__ void k_dgather(const float* __restrict__ h, const float* __restrict__ cur,
                          float* __restrict__ outH, float* __restrict__ outC, int n) {
    __shared__ int ssmax;
    int tid = threadIdx.x;
    if (tid == 0) ssmax = 0;
    __syncthreads();

    int hw = (blockIdx.x * blockDim.x + tid) >> 4;
    int lane = tid & 15;
    bool valid = (hw < n);
    int d = valid ? g_deg[hw] : 0;
    int dc = min(d, SLOT);
    int base = hw * SLOT;
    const float4* h4 = (const float4*)h;
    const float4* c4 = (const float4*)cur;
    float hx = 0.f, hy = 0.f, hz = 0.f, hw_ = 0.f;
    float cx = 0.f, cy = 0.f, cz = 0.f, cw = 0.f;
    int i = 0;
    for (; i + 4 <= dc; i += 4) {
        int s0 = __ldg(&g_srcpad[base + i]);
        int s1 = __ldg(&g_srcpad[base + i + 1]);
        int s2 = __ldg(&g_srcpad[base + i + 2]);
        int s3 = __ldg(&g_srcpad[base + i + 3]);
        float4 a0 = __ldg(&h4[s0 * 16 + lane]);
        float4 a1 = __ldg(&h4[s1 * 16 + lane]);
        float4 a2 = __ldg(&h4[s2 * 16 + lane]);
        float4 a3 = __ldg(&h4[s3 * 16 + lane]);
        float4 b0 = __ldg(&c4[s0 * 16 + lane]);
        float4 b1 = __ldg(&c4[s1 * 16 + lane]);
        float4 b2 = __ldg(&c4[s2 * 16 + lane]);
        float4 b3 = __ldg(&c4[s3 * 16 + lane]);
        hx += (a0.x + a1.x) + (a2.x + a3.x);
        hy += (a0.y + a1.y) + (a2.y + a3.y);
        hz += (a0.z + a1.z) + (a2.z + a3.z);
        hw_ += (a0.w + a1.w) + (a2.w + a3.w);
        cx += (b0.x + b1.x) + (b2.x + b3.x);
        cy += (b0.y + b1.y) + (b2.y + b3.y);
        cz += (b0.z + b1.z) + (b2.z + b3.z);
        cw += (b0.w + b1.w) + (b2.w + b3.w);
    }
    for (; i < dc; i++) {
        int s = __ldg(&g_srcpad[base + i]);
        float4 a = __ldg(&h4[s * 16 + lane]);
        float4 b = __ldg(&c4[s * 16 + lane]);
        hx += a.x; hy += a.y; hz += a.z; hw_ += a.w;
        cx += b.x; cy += b.y; cz += b.z; cw += b.w;
    }
    if (valid) {
        float sc = (d > 0) ? (1.0f / (float)d) : 0.0f;
        hx *= sc; hy *= sc; hz *= sc; hw_ *= sc;
        cx *= sc; cy *= sc; cz *= sc; cw *= sc;
        if (lane == 15) hw_ = 0.f;   // patched to deg/degmax in k_gemm64 staging
        ((float4*)outH)[hw * 16 + lane] = make_float4(hx, hy, hz, hw_);
        ((float4*)outC)[hw * 16 + lane] = make_float4(cx, cy, cz, cw);
    }
    if (lane == 0 && valid) atomicMax(&ssmax, d);
    __syncthreads();
    if (tid == 0) atomicMax(&g_degmax, ssmax);
}

__global__ void k_gather(const float* __restrict__ feat, float* __restrict__ out, int n) {
    int hw = (blockIdx.x * blockDim.x + threadIdx.x) >> 4;
    int lane = threadIdx.x & 15;
    if (hw >= n) return;
    int d = g_deg[hw];
    int dc = min(d, SLOT);
    int base = hw * SLOT;
    const float4* f4 = (const float4*)feat;
    float ax = 0.f, ay = 0.f, az = 0.f, aw = 0.f;
    int i = 0;
    for (; i + 4 <= dc; i += 4) {
        int s0 = __ldg(&g_srcpad[base + i]);
        int s1 = __ldg(&g_srcpad[base + i + 1]);
        int s2 = __ldg(&g_srcpad[base + i + 2]);
        int s3 = __ldg(&g_srcpad[base + i + 3]);
        float4 v0 = __ldg(&f4[s0 * 16 + lane]);
        float4 v1 = __ldg(&f4[s1 * 16 + lane]);
        float4 v2 = __ldg(&f4[s2 * 16 + lane]);
        float4 v3 = __ldg(&f4[s3 * 16 + lane]);
        ax += (v0.x + v1.x) + (v2.x + v3.x);
        ay += (v0.y + v1.y) + (v2.y + v3.y);
        az += (v0.z + v1.z) + (v2.z + v3.z);
        aw += (v0.w + v1.w) + (v2.w + v3.w);
    }
    for (; i < dc; i++) {
        int s = __ldg(&g_srcpad[base + i]);
        float4 v = __ldg(&f4[s * 16 + lane]);
        ax += v.x; ay += v.y; az += v.z; aw += v.w;
    }
    float sc = (d > 0) ? (1.0f / (float)d) : 0.0f;
    ((float4*)out)[hw * 16 + lane] = make_float4(ax * sc, ay * sc, az * sc, aw * sc);
}

// ----------------------------- mma.sync layer -------------------------------
// Bf layout: [kstep s][lane l][20] (16 used): Bf[(s*32+l)*20 + 2j]   = W[8s+lq][lg+8j]
//                                             Bf[(s*32+l)*20 + 2j+1] = W[8s+lq+4][lg+8j]
__device__ __forceinline__ void stage_Bf(float* __restrict__ Bf,
                                         const float* __restrict__ W, int tid) {
    for (int slot = tid; slot < 512; slot += 256) {
        int s = slot >> 5, l = slot & 31;
        int kr0 = 8 * s + (l & 3);
        int nc  = (l >> 2);
        float* dst = &Bf[slot * 20];
#pragma unroll
        for (int j = 0; j < 8; j++) {
            dst[2 * j]     = __uint_as_float(tf32r(__ldg(&W[(size_t)kr0 * 64 + nc + 8 * j])));
            dst[2 * j + 1] = __uint_as_float(tf32r(__ldg(&W[(size_t)(kr0 + 4) * 64 + nc + 8 * j])));
        }
    }
}

__device__ __forceinline__ uint32_t ldA(const float* __restrict__ src, int node,
                                        int c, int n) {
    return (node < n) ? tf32r(__ldg(&src[(size_t)node * 64 + c])) : 0u;
}

#define MSGP 68   // msgbuf pitch (floats): (4*rowgroup + col) distinct banks

template <bool LAST>
__global__ __launch_bounds__(256) void k_layer_mma(const float* __restrict__ nagg,
                                                   const float* __restrict__ eemb,
                                                   const float* __restrict__ cur,
                                                   const float* __restrict__ Wmsg,
                                                   const float* __restrict__ Wupd,
                                                   float* __restrict__ cout,
                                                   const float* __restrict__ Wr,
                                                   const int* __restrict__ batch,
                                                   float* __restrict__ out, int n) {
    extern __shared__ float sm[];
    float* Bf     = sm;            // 512*20 = 10240 floats (40KB)
    float* msgbuf = sm + 10240;    // 128*68 = 8704 floats (34KB)
    __shared__ float Wrs[64];

    int tid = threadIdx.x;
    int w = tid >> 5;
    int l = tid & 31;
    int lg = l >> 2;      // row group 0..7
    int lq = l & 3;       // quad id 0..3
    int r0 = 16 * w + lg; // local row of d0/d1; d2/d3 at r0+8
    int node0 = blockIdx.x * 128;

    if (LAST && tid < 64) Wrs[tid] = __ldg(&Wr[64 + tid]);
    stage_Bf(Bf, Wmsg, tid);
    __syncthreads();

    float acc[8][4];
#pragma unroll
    for (int j = 0; j < 8; j++)
#pragma unroll
        for (int m = 0; m < 4; m++) acc[j][m] = 0.f;

    // ---- phase 1: msg = relu( concat(nagg, eemb) @ Wmsg )
#pragma unroll 4
    for (int s = 0; s < 16; s++) {
        int c = 8 * s + lq;
        uint32_t a0, a1, a2, a3;
        if (s < 8) {
            a0 = ldA(nagg, node0 + r0, c, n);
            a1 = ldA(nagg, node0 + r0 + 8, c, n);
            a2 = ldA(nagg, node0 + r0, c + 4, n);
            a3 = ldA(nagg, node0 + r0 + 8, c + 4, n);
        } else {
            a0 = ldA(eemb, node0 + r0, c - 64, n);
            a1 = ldA(eemb, node0 + r0 + 8, c - 64, n);
            a2 = ldA(eemb, node0 + r0, c - 60, n);
            a3 = ldA(eemb, node0 + r0 + 8, c - 60, n);
        }
        const uint4* bp = (const uint4*)&Bf[(s * 32 + l) * 20];
        uint4 b0 = bp[0], b1 = bp[1], b2 = bp[2], b3 = bp[3];
        mma_tf32(acc[0], a0, a1, a2, a3, b0.x, b0.y);
        mma_tf32(acc[1], a0, a1, a2, a3, b0.z, b0.w);
        mma_tf32(acc[2], a0, a1, a2, a3, b1.x, b1.y);
        mma_tf32(acc[3], a0, a1, a2, a3, b1.z, b1.w);
        mma_tf32(acc[4], a0, a1, a2, a3, b2.x, b2.y);
        mma_tf32(acc[5], a0, a1, a2, a3, b2.z, b2.w);
        mma_tf32(acc[6], a0, a1, a2, a3, b3.x, b3.y);
        mma_tf32(acc[7], a0, a1, a2, a3, b3.z, b3.w);
    }

    // relu(msg) -> msgbuf
#pragma unroll
    for (int j = 0; j < 8; j++) {
        int c = 8 * j + 2 * lq;
        *(float2*)&msgbuf[r0 * MSGP + c] =
            make_float2(fmaxf(acc[j][0], 0.f), fmaxf(acc[j][1], 0.f));
        *(float2*)&msgbuf[(r0 + 8) * MSGP + c] =
            make_float2(fmaxf(acc[j][2], 0.f), fmaxf(acc[j][3], 0.f));
    }
    __syncthreads();
    stage_Bf(Bf, Wupd, tid);
#pragma unroll
    for (int j = 0; j < 8; j++)
#pragma unroll
        for (int m = 0; m < 4; m++) acc[j][m] = 0.f;
    __syncthreads();

    // ---- phase 2: cout = relu( concat(cur, msg) @ Wupd )
#pragma unroll 4
    for (int s = 0; s < 16; s++) {
        int c = 8 * s + lq;
        uint32_t a0, a1, a2, a3;
        if (s < 8) {
            a0 = ldA(cur, node0 + r0, c, n);
            a1 = ldA(cur, node0 + r0 + 8, c, n);
            a2 = ldA(cur, node0 + r0, c + 4, n);
            a3 = ldA(cur, node0 + r0 + 8, c + 4, n);
        } else {
            a0 = tf32r(msgbuf[r0 * MSGP + (c - 64)]);
            a1 = tf32r(msgbuf[(r0 + 8) * MSGP + (c - 64)]);
            a2 = tf32r(msgbuf[r0 * MSGP + (c - 60)]);
            a3 = tf32r(msgbuf[(r0 + 8) * MSGP + (c - 60)]);
        }
        const uint4* bp = (const uint4*)&Bf[(s * 32 + l) * 20];
        uint4 b0 = bp[0], b1 = bp[1], b2 = bp[2], b3 = bp[3];
        mma_tf32(acc[0], a0, a1, a2, a3, b0.x, b0.y);
        mma_tf32(acc[1], a0, a1, a2, a3, b0.z, b0.w);
        mma_tf32(acc[2], a0, a1, a2, a3, b1.x, b1.y);
        mma_tf32(acc[3], a0, a1, a2, a3, b1.z, b1.w);
        mma_tf32(acc[4], a0, a1, a2, a3, b2.x, b2.y);
        mma_tf32(acc[5], a0, a1, a2, a3, b2.z, b2.w);
        mma_tf32(acc[6], a0, a1, a2, a3, b3.x, b3.y);
        mma_tf32(acc[7], a0, a1, a2, a3, b3.z, b3.w);
    }

    if (!LAST) {
        int nodeA = node0 + r0;
        int nodeB = node0 + r0 + 8;
#pragma unroll
        for (int j = 0; j < 8; j++) {
            int c = 8 * j + 2 * lq;
            if (nodeA < n)
                *(float2*)&cout[(size_t)nodeA * 64 + c] =
                    make_float2(fmaxf(acc[j][0], 0.f), fmaxf(acc[j][1], 0.f));
            if (nodeB < n)
                *(float2*)&cout[(size_t)nodeB * 64 + c] =
                    make_float2(fmaxf(acc[j][2], 0.f), fmaxf(acc[j][3], 0.f));
        }
    } else {
        // per-node dot with W_read[64:]
        float dv0 = 0.f, dv1 = 0.f;
#pragma unroll
        for (int j = 0; j < 8; j++) {
            int c = 8 * j + 2 * lq;
            float w0 = Wrs[c], w1 = Wrs[c + 1];
            dv0 += fmaxf(acc[j][0], 0.f) * w0 + fmaxf(acc[j][1], 0.f) * w1;
            dv1 += fmaxf(acc[j][2], 0.f) * w0 + fmaxf(acc[j][3], 0.f) * w1;
        }
        dv0 += __shfl_xor_sync(0xffffffffu, dv0, 1);
        dv0 += __shfl_xor_sync(0xffffffffu, dv0, 2);
        dv1 += __shfl_xor_sync(0xffffffffu, dv1, 1);
        dv1 += __shfl_xor_sync(0xffffffffu, dv1, 2);
        if (lq == 0) {
            if (node0 + r0 < n)     out[node0 + r0]     = dv0;
            if (node0 + r0 + 8 < n) out[node0 + r0 + 8] = dv1;
        }
        // relu'd rows -> msgbuf for segmented per-graph reduce
        __syncthreads();
#pragma unroll
        for (int j = 0; j < 8; j++) {
            int c = 8 * j + 2 * lq;
            *(float2*)&msgbuf[r0 * MSGP + c] =
                make_float2(fmaxf(acc[j][0], 0.f), fmaxf(acc[j][1], 0.f));
            *(float2*)&msgbuf[(r0 + 8) * MSGP + c] =
                make_float2(fmaxf(acc[j][2], 0.f), fmaxf(acc[j][3], 0.f));
        }
        __syncthreads();
        if (tid < 64) {
            int c = tid;
            float acc2 = 0.f, cnt = 0.f;
            int curb = -1;
            for (int i = 0; i < 128; i++) {
                int nd = node0 + i;
                if (nd >= n) break;
                int b = __ldg(&batch[nd]);
                if (b != curb) {
                    if (curb >= 0) {
                        atomicAdd(&g_means[curb * 64 + c], acc2);
                        if (c == 0) atomicAdd(&g_cnt[curb], cnt);
                    }
                    acc2 = 0.f; cnt = 0.f; curb = b;
                }
                acc2 += msgbuf[i * MSGP + c];
                cnt += 1.f;
            }
            if (curb >= 0) {
                atomicAdd(&g_means[curb * 64 + c], acc2);
                if (c == 0) atomicAdd(&g_cnt[curb], cnt);
            }
        }
    }
}

// ------------------------- FFMA2 GEMM (edge embedding) ---------------------
template <int K, int PITCH>
__device__ __forceinline__ void gemm_core8x8(const float* __restrict__ ins,
                                             const float* __restrict__ Ws,
                                             ull acc[8][4]) {
    int q  = threadIdx.x & 7;
    int rr = threadIdx.x >> 3;
#pragma unroll
    for (int j = 0; j < 8; j++)
#pragma unroll
        for (int m = 0; m < 4; m++) acc[j][m] = 0ull;

#pragma unroll 1
    for (int k = 0; k < K; k += 4) {
        float4 a[8];
#pragma unroll
        for (int j = 0; j < 8; j++)
            a[j] = *(const float4*)&ins[(rr + 16 * j) * PITCH + k];
#pragma unroll
        for (int kk = 0; kk < 4; kk++) {
            ulonglong2 w = *(const ulonglong2*)&Ws[(k + kk) * 64 + q * 8];
            ulonglong2 w2 = *(const ulonglong2*)&Ws[(k + kk) * 64 + q * 8 + 4];
#pragma unroll
            for (int j = 0; j < 8; j++) {
                float av = (kk == 0) ? a[j].x : (kk == 1) ? a[j].y
                         : (kk == 2) ? a[j].z : a[j].w;
                ull p;
                asm("mov.b64 %0, {%1, %1};" : "=l"(p) : "f"(av));
                asm("fma.rn.f32x2 %0, %1, %2, %0;" : "+l"(acc[j][0]) : "l"(p), "l"(w.x));
                asm("fma.rn.f32x2 %0, %1, %2, %0;" : "+l"(acc[j][1]) : "l"(p), "l"(w.y));
                asm("fma.rn.f32x2 %0, %1, %2, %0;" : "+l"(acc[j][2]) : "l"(p), "l"(w2.x));
                asm("fma.rn.f32x2 %0, %1, %2, %0;" : "+l"(acc[j][3]) : "l"(p), "l"(w2.y));
            }
        }
    }
}

__device__ __forceinline__ float4 acc_relu4(ull a0, ull a1) {
    float lo0, hi0, lo1, hi1;
    asm("mov.b64 {%0, %1}, %2;" : "=f"(lo0), "=f"(hi0) : "l"(a0));
    asm("mov.b64 {%0, %1}, %2;" : "=f"(lo1), "=f"(hi1) : "l"(a1));
    float4 o;
    o.x = fmaxf(lo0, 0.f); o.y = fmaxf(hi0, 0.f);
    o.z = fmaxf(lo1, 0.f); o.w = fmaxf(hi1, 0.f);
    return o;
}

// eemb = relu( naggH @ We2 ), K=64; staging patches col 63 = deg/degmax
__global__ __launch_bounds__(128) void k_gemm64(const float* __restrict__ A,
                                                const float* __restrict__ W,
                                                float* __restrict__ C, int n) {
    extern __shared__ float sm[];
    const int PITCH = 68;
    float* Ws  = sm;
    float* ins = sm + 64 * 64;
    int tid = threadIdx.x;
    int node0 = blockIdx.x * 128;
    float dmx = (float)max(g_degmax, 1);

    for (int idx = tid; idx < 64 * 16; idx += 128)
        ((float4*)Ws)[idx] = __ldg((const float4*)W + idx);
    for (int idx = tid; idx < 2048; idx += 128) {
        int r = idx >> 4, c4 = (idx & 15) << 2;
        int node = node0 + r;
        float4 va = make_float4(0.f, 0.f, 0.f, 0.f);
        if (node < n) {
            va = __ldg((const float4*)&A[(size_t)node * 64 + c4]);
            if (c4 == 60) va.w = (float)g_deg[node] / dmx;
        }
        *(float4*)&ins[r * PITCH + c4] = va;
    }
    __syncthreads();

    ull acc[8][4];
    gemm_core8x8<64, PITCH>(ins, Ws, acc);

    int q  = tid & 7;
    int rr = tid >> 3;
#pragma unroll
    for (int j = 0; j < 8; j++) {
        int node = node0 + rr + 16 * j;
        if (node < n) {
            float* Cr = &C[(size_t)node * 64 + q * 8];
            *(float4*)&Cr[0] = acc_relu4(acc[j][0], acc[j][1]);
            *(float4*)&Cr[4] = acc_relu4(acc[j][2], acc[j][3]);
        }
    }
}

// ------------------------------- readout -----------------------------------
__global__ void k_gconst(const float* __restrict__ Wp, const float* __restrict__ Wr,
                         const float* __restrict__ br) {
    int g = blockIdx.x;
    int t = threadIdx.x;
    __shared__ float m[64];
    __shared__ float red[64];
    float cnt = g_cnt[g];
    if (cnt <= 0.f) { if (t == 0) g_gconst[g] = 0.f; return; }
    m[t] = g_means[g * 64 + t] / cnt;
    __syncthreads();
    float p = 0.f;
#pragma unroll 8
    for (int k = 0; k < 64; k++) p += m[k] * __ldg(&Wp[k * 64 + t]);
    red[t] = fmaxf(p, 0.f) * __ldg(&Wr[t]);
    __syncthreads();
    if (t < 32) {
        float s = red[t] + red[t + 32];
#pragma unroll
        for (int off = 16; off > 0; off >>= 1) s += __shfl_down_sync(0xffffffffu, s, off);
        if (t == 0) g_gconst[g] = s + __ldg(&br[0]);
    }
}

__global__ void k_addg(const int* __restrict__ batch, float* __restrict__ out, int n) {
    int i = blockIdx.x * blockDim.x + threadIdx.x;
    if (i < n) out[i] += g_gconst[__ldg(&batch[i])];
}

// ---------------------------------------------------------------------------
extern "C" void kernel_launch(void* const* d_in, const int* in_sizes, int n_in,
                              void* d_out, int out_size) {
    const float* x    = (const float*)d_in[0];
    const float* Wi   = (const float*)d_in[1];
    const float* We1  = (const float*)d_in[2];
    const float* We2  = (const float*)d_in[3];
    const float* Wmsg = (const float*)d_in[4];
    const float* Wupd = (const float*)d_in[5];
    const float* Wp   = (const float*)d_in[6];
    const float* Wr   = (const float*)d_in[7];
    const float* br   = (const float*)d_in[8];
    const int*   eidx = (const int*)d_in[9];
    const int*   batch= (const int*)d_in[10];

    int n    = in_sizes[10];
    int E    = in_sizes[9] / 2;
    int nobs = in_sizes[0] / n;
    int L    = in_sizes[4] / (128 * 64);
    const int* row = eidx;
    const int* col = eidx + E;
    float* out = (float*)d_out;

    float *curA, *curB, *hbuf, *nagg, *naggH, *eemb, *means, *cnt;
    int *deg, *degmax;
    cudaGetSymbolAddress((void**)&curA, g_curA);
    cudaGetSymbolAddress((void**)&curB, g_curB);
    cudaGetSymbolAddress((void**)&hbuf, g_h);
    cudaGetSymbolAddress((void**)&nagg, g_nagg);
    cudaGetSymbolAddress((void**)&naggH, g_naggH);
    cudaGetSymbolAddress((void**)&eemb, g_eemb);
    cudaGetSymbolAddress((void**)&means, g_means);
    cudaGetSymbolAddress((void**)&cnt,   g_cnt);
    cudaGetSymbolAddress((void**)&deg,   g_deg);
    cudaGetSymbolAddress((void**)&degmax, g_degmax);

    const int SMEM_MMA = (10240 + 128 * 68) * 4;  // Bf 40KB + msgbuf 34KB = 75776
    const int SMEM64   = (64 * 64 + 128 * 68) * 4;
    cudaFuncSetAttribute(k_layer_mma<false>, cudaFuncAttributeMaxDynamicSharedMemorySize, SMEM_MMA);
    cudaFuncSetAttribute(k_layer_mma<true>,  cudaFuncAttributeMaxDynamicSharedMemorySize, SMEM_MMA);
    cudaFuncSetAttribute(k_gemm64, cudaFuncAttributeMaxDynamicSharedMemorySize, SMEM64);

    int gFI = (E + n * 64 + 255) / 256;
    int gHW = (n * 16 + 255) / 256;
    int gG  = (n + 127) / 128;
    int gA  = (n + 255) / 256;

    cudaMemsetAsync(deg,    0, (size_t)n * sizeof(int));
    cudaMemsetAsync(degmax, 0, sizeof(int));
    cudaMemsetAsync(means,  0, (size_t)MAXG * FD * sizeof(float));
    cudaMemsetAsync(cnt,    0, (size_t)MAXG * sizeof(float));

    k_fillpad<<<gFI, 256>>>(row, col, x, Wi, We1, E, n, nobs);   // kernel 1
    k_dgather<<<gHW, 256>>>(hbuf, curA, naggH, nagg, n);         // kernel 2
    k_gemm64<<<gG, 128, SMEM64>>>(naggH, We2, eemb, n);          // kernel 3

    float* cin = curA;
    float* cout = curB;
    for (int l = 0; l < L; l++) {
        bool last = (l == L - 1);
        if (l > 0) k_gather<<<gHW, 256>>>(cin, nagg, n);
        if (!last) {
            k_layer_mma<false><<<gG, 256, SMEM_MMA>>>(nagg, eemb, cin,   // kernel 4 (l=0): profiled
                                                      Wmsg + (size_t)l * 8192,
                                                      Wupd + (size_t)l * 8192,
                                                      cout, nullptr, nullptr, nullptr, n);
            float* tmp = cin; cin = cout; cout = tmp;
        } else {
            k_layer_mma<true><<<gG, 256, SMEM_MMA>>>(nagg, eemb, cin,
                                                     Wmsg + (size_t)l * 8192,
                                                     Wupd + (size_t)l * 8192,
                                                     nullptr, Wr, batch, out, n);
        }
    }

    k_gconst<<<MAXG, 64>>>(Wp, Wr, br);
    k_addg<<<gA, 256>>>(batch, out, n);
}

// round 13
// speedup vs baseline: 1.8205x; 1.0382x over previous
#include <cuda_runtime.h>
#include <cuda_bf16.h>
#include <cstdint>
#include <math.h>

// ---------------------------------------------------------------------------
// MPNN on GB300 (round 13 = round 12 +):
//  - k_layer_mma: PreferredSharedMemoryCarveout=100 -> 3 blocks/SM
//    (3 x 75776B = 227328B fits the 228KB carveout), killing the tail wave
//    and raising warps/SM 16 -> 24 on the latency-bound layer kernel.
//  - Gathers: unroll 8 for deeper MLP (latency-bound at issue=30%).
//  - Layer GEMMs stay on mma.sync m16n8k8 tf32 (rel_err 6.4e-4, margin held).
// ---------------------------------------------------------------------------

#define MAXN 65536
#define MAXG 512
#define FD   64
#define SLOT 96

typedef unsigned long long ull;

__device__ int   g_deg[MAXN];
__device__ int   g_srcpad[MAXN * SLOT];
__device__ int   g_degmax;

__device__ float g_h[MAXN * FD];
__device__ float g_nagg[MAXN * FD];
__device__ float g_naggH[MAXN * FD];
__device__ float g_eemb[MAXN * FD];
__device__ float g_curA[MAXN * FD];
__device__ float g_curB[MAXN * FD];

__device__ float g_means[MAXG * FD];
__device__ float g_cnt[MAXG];
__device__ float g_gconst[MAXG];

// ----------------------------- helpers ------------------------------------
__device__ __forceinline__ uint32_t tf32r(float x) {
    uint32_t y;
    asm("cvt.rna.tf32.f32 %0, %1;" : "=r"(y) : "f"(x));
    return y;
}

__device__ __forceinline__ void mma_tf32(float acc[4], uint32_t a0, uint32_t a1,
                                         uint32_t a2, uint32_t a3,
                                         uint32_t b0, uint32_t b1) {
    asm volatile("mma.sync.aligned.m16n8k8.row.col.f32.tf32.tf32.f32 "
                 "{%0,%1,%2,%3}, {%4,%5,%6,%7}, {%8,%9}, {%0,%1,%2,%3};"
                 : "+f"(acc[0]), "+f"(acc[1]), "+f"(acc[2]), "+f"(acc[3])
                 : "r"(a0), "r"(a1), "r"(a2), "r"(a3), "r"(b0), "r"(b1));
}

// ----------------------------- structure build -----------------------------
__global__ void k_fillpad(const int* __restrict__ row, const int* __restrict__ col,
                          const float* __restrict__ x, const float* __restrict__ Wi,
                          const float* __restrict__ We1, int E, int n, int nobs) {
    int i = blockIdx.x * blockDim.x + threadIdx.x;
    if (i < E) {
        int c = col[i];
        int p = atomicAdd(&g_deg[c], 1);
        if (p < SLOT) g_srcpad[c * SLOT + p] = row[i];
    } else {
        int t = i - E;
        if (t >= n * 64) return;
        int node = t >> 6, c = t & 63;
        const float* xr = x + node * nobs;
        float s1 = 0.f, s2 = 0.f;
        for (int j = 0; j < nobs; j++) {
            float xv = __ldg(&xr[j]);
            s1 += xv * __ldg(&Wi[j * 64 + c]);
            if (c < 63) s2 += xv * __ldg(&We1[j * 63 + c]);
        }
        g_curA[t] = fmaxf(s1, 0.f);
        g_h[t]    = (c < 63) ? fmaxf(s2, 0.f) : 0.f;
    }
}

__global__ void k_dgather(const float* __restrict__ h, const float* __restrict__ cur,
                          float* __restrict__ outH, float* __restrict__ outC, int n) {
    __shared__ int ssmax;
    int tid = threadIdx.x;
    if (tid == 0) ssmax = 0;
    __syncthreads();

    int hw = (blockIdx.x * blockDim.x + tid) >> 4;
    int lane = tid & 15;
    bool valid = (hw < n);
    int d = valid ? g_deg[hw] : 0;
    int dc = min(d, SLOT);
    int base = hw * SLOT;
    const float4* h4 = (const float4*)h;
    const float4* c4 = (const float4*)cur;
    float hx = 0.f, hy = 0.f, hz = 0.f, hw_ = 0.f;
    float cx = 0.f, cy = 0.f, cz = 0.f, cw = 0.f;
    int i = 0;
    for (; i + 8 <= dc; i += 8) {
        int s[8];
#pragma unroll
        for (int u = 0; u < 8; u++) s[u] = __ldg(&g_srcpad[base + i + u]);
        float4 a[8], b[8];
#pragma unroll
        for (int u = 0; u < 8; u++) {
            a[u] = __ldg(&h4[s[u] * 16 + lane]);
            b[u] = __ldg(&c4[s[u] * 16 + lane]);
        }
#pragma unroll
        for (int u = 0; u < 8; u++) {
            hx += a[u].x; hy += a[u].y; hz += a[u].z; hw_ += a[u].w;
            cx += b[u].x; cy += b[u].y; cz += b[u].z; cw += b[u].w;
        }
    }
    for (; i < dc; i++) {
        int s = __ldg(&g_srcpad[base + i]);
        float4 a = __ldg(&h4[s * 16 + lane]);
        float4 b = __ldg(&c4[s * 16 + lane]);
        hx += a.x; hy += a.y; hz += a.z; hw_ += a.w;
        cx += b.x; cy += b.y; cz += b.z; cw += b.w;
    }
    if (valid) {
        float sc = (d > 0) ? (1.0f / (float)d) : 0.0f;
        hx *= sc; hy *= sc; hz *= sc; hw_ *= sc;
        cx *= sc; cy *= sc; cz *= sc; cw *= sc;
        if (lane == 15) hw_ = 0.f;   // patched to deg/degmax in k_gemm64 staging
        ((float4*)outH)[hw * 16 + lane] = make_float4(hx, hy, hz, hw_);
        ((float4*)outC)[hw * 16 + lane] = make_float4(cx, cy, cz, cw);
    }
    if (lane == 0 && valid) atomicMax(&ssmax, d);
    __syncthreads();
    if (tid == 0) atomicMax(&g_degmax, ssmax);
}

__global__ void k_gather(const float* __restrict__ feat, float* __restrict__ out, int n) {
    int hw = (blockIdx.x * blockDim.x + threadIdx.x) >> 4;
    int lane = threadIdx.x & 15;
    if (hw >= n) return;
    int d = g_deg[hw];
    int dc = min(d, SLOT);
    int base = hw * SLOT;
    const float4* f4 = (const float4*)feat;
    float ax = 0.f, ay = 0.f, az = 0.f, aw = 0.f;
    int i = 0;
    for (; i + 8 <= dc; i += 8) {
        int s[8];
#pragma unroll
        for (int u = 0; u < 8; u++) s[u] = __ldg(&g_srcpad[base + i + u]);
        float4 v[8];
#pragma unroll
        for (int u = 0; u < 8; u++) v[u] = __ldg(&f4[s[u] * 16 + lane]);
#pragma unroll
        for (int u = 0; u < 8; u++) {
            ax += v[u].x; ay += v[u].y; az += v[u].z; aw += v[u].w;
        }
    }
    for (; i < dc; i++) {
        int s = __ldg(&g_srcpad[base + i]);
        float4 v = __ldg(&f4[s * 16 + lane]);
        ax += v.x; ay += v.y; az += v.z; aw += v.w;
    }
    float sc = (d > 0) ? (1.0f / (float)d) : 0.0f;
    ((float4*)out)[hw * 16 + lane] = make_float4(ax * sc, ay * sc, az * sc, aw * sc);
}

// ----------------------------- mma.sync layer -------------------------------
// Bf layout: [kstep s][lane l][20] (16 used): Bf[(s*32+l)*20 + 2j]   = W[8s+lq][lg+8j]
//                                             Bf[(s*32+l)*20 + 2j+1] = W[8s+lq+4][lg+8j]
__device__ __forceinline__ void stage_Bf(float* __restrict__ Bf,
                                         const float* __restrict__ W, int tid) {
    for (int slot = tid; slot < 512; slot += 256) {
        int s = slot >> 5, l = slot & 31;
        int kr0 = 8 * s + (l & 3);
        int nc  = (l >> 2);
        float* dst = &Bf[slot * 20];
#pragma unroll
        for (int j = 0; j < 8; j++) {
            dst[2 * j]     = __uint_as_float(tf32r(__ldg(&W[(size_t)kr0 * 64 + nc + 8 * j])));
            dst[2 * j + 1] = __uint_as_float(tf32r(__ldg(&W[(size_t)(kr0 + 4) * 64 + nc + 8 * j])));
        }
    }
}

__device__ __forceinline__ uint32_t ldA(const float* __restrict__ src, int node,
                                        int c, int n) {
    return (node < n) ? tf32r(__ldg(&src[(size_t)node * 64 + c])) : 0u;
}

#define MSGP 68   // msgbuf pitch (floats)

template <bool LAST>
__global__ __launch_bounds__(256) void k_layer_mma(const float* __restrict__ nagg,
                                                   const float* __restrict__ eemb,
                                                   const float* __restrict__ cur,
                                                   const float* __restrict__ Wmsg,
                                                   const float* __restrict__ Wupd,
                                                   float* __restrict__ cout,
                                                   const float* __restrict__ Wr,
                                                   const int* __restrict__ batch,
                                                   float* __restrict__ out, int n) {
    extern __shared__ float sm[];
    float* Bf     = sm;            // 512*20 = 10240 floats (40KB)
    float* msgbuf = sm + 10240;    // 128*68 = 8704 floats (34KB)
    __shared__ float Wrs[64];

    int tid = threadIdx.x;
    int w = tid >> 5;
    int l = tid & 31;
    int lg = l >> 2;      // row group 0..7
    int lq = l & 3;       // quad id 0..3
    int r0 = 16 * w + lg; // local row of d0/d1; d2/d3 at r0+8
    int node0 = blockIdx.x * 128;

    if (LAST && tid < 64) Wrs[tid] = __ldg(&Wr[64 + tid]);
    stage_Bf(Bf, Wmsg, tid);
    __syncthreads();

    float acc[8][4];
#pragma unroll
    for (int j = 0; j < 8; j++)
#pragma unroll
        for (int m = 0; m < 4; m++) acc[j][m] = 0.f;

    // ---- phase 1: msg = relu( concat(nagg, eemb) @ Wmsg )
#pragma unroll 4
    for (int s = 0; s < 16; s++) {
        int c = 8 * s + lq;
        uint32_t a0, a1, a2, a3;
        if (s < 8) {
            a0 = ldA(nagg, node0 + r0, c, n);
            a1 = ldA(nagg, node0 + r0 + 8, c, n);
            a2 = ldA(nagg, node0 + r0, c + 4, n);
            a3 = ldA(nagg, node0 + r0 + 8, c + 4, n);
        } else {
            a0 = ldA(eemb, node0 + r0, c - 64, n);
            a1 = ldA(eemb, node0 + r0 + 8, c - 64, n);
            a2 = ldA(eemb, node0 + r0, c - 60, n);
            a3 = ldA(eemb, node0 + r0 + 8, c - 60, n);
        }
        const uint4* bp = (const uint4*)&Bf[(s * 32 + l) * 20];
        uint4 b0 = bp[0], b1 = bp[1], b2 = bp[2], b3 = bp[3];
        mma_tf32(acc[0], a0, a1, a2, a3, b0.x, b0.y);
        mma_tf32(acc[1], a0, a1, a2, a3, b0.z, b0.w);
        mma_tf32(acc[2], a0, a1, a2, a3, b1.x, b1.y);
        mma_tf32(acc[3], a0, a1, a2, a3, b1.z, b1.w);
        mma_tf32(acc[4], a0, a1, a2, a3, b2.x, b2.y);
        mma_tf32(acc[5], a0, a1, a2, a3, b2.z, b2.w);
        mma_tf32(acc[6], a0, a1, a2, a3, b3.x, b3.y);
        mma_tf32(acc[7], a0, a1, a2, a3, b3.z, b3.w);
    }

    // relu(msg) -> msgbuf
#pragma unroll
    for (int j = 0; j < 8; j++) {
        int c = 8 * j + 2 * lq;
        *(float2*)&msgbuf[r0 * MSGP + c] =
            make_float2(fmaxf(acc[j][0], 0.f), fmaxf(acc[j][1], 0.f));
        *(float2*)&msgbuf[(r0 + 8) * MSGP + c] =
            make_float2(fmaxf(acc[j][2], 0.f), fmaxf(acc[j][3], 0.f));
    }
    __syncthreads();
    stage_Bf(Bf, Wupd, tid);
#pragma unroll
    for (int j = 0; j < 8; j++)
#pragma unroll
        for (int m = 0; m < 4; m++) acc[j][m] = 0.f;
    __syncthreads();

    // ---- phase 2: cout = relu( concat(cur, msg) @ Wupd )
#pragma unroll 4
    for (int s = 0; s < 16; s++) {
        int c = 8 * s + lq;
        uint32_t a0, a1, a2, a3;
        if (s < 8) {
            a0 = ldA(cur, node0 + r0, c, n);
            a1 = ldA(cur, node0 + r0 + 8, c, n);
            a2 = ldA(cur, node0 + r0, c + 4, n);
            a3 = ldA(cur, node0 + r0 + 8, c + 4, n);
        } else {
            a0 = tf32r(msgbuf[r0 * MSGP + (c - 64)]);
            a1 = tf32r(msgbuf[(r0 + 8) * MSGP + (c - 64)]);
            a2 = tf32r(msgbuf[r0 * MSGP + (c - 60)]);
            a3 = tf32r(msgbuf[(r0 + 8) * MSGP + (c - 60)]);
        }
        const uint4* bp = (const uint4*)&Bf[(s * 32 + l) * 20];
        uint4 b0 = bp[0], b1 = bp[1], b2 = bp[2], b3 = bp[3];
        mma_tf32(acc[0], a0, a1, a2, a3, b0.x, b0.y);
        mma_tf32(acc[1], a0, a1, a2, a3, b0.z, b0.w);
        mma_tf32(acc[2], a0, a1, a2, a3, b1.x, b1.y);
        mma_tf32(acc[3], a0, a1, a2, a3, b1.z, b1.w);
        mma_tf32(acc[4], a0, a1, a2, a3, b2.x, b2.y);
        mma_tf32(acc[5], a0, a1, a2, a3, b2.z, b2.w);
        mma_tf32(acc[6], a0, a1, a2, a3, b3.x, b3.y);
        mma_tf32(acc[7], a0, a1, a2, a3, b3.z, b3.w);
    }

    if (!LAST) {
        int nodeA = node0 + r0;
        int nodeB = node0 + r0 + 8;
#pragma unroll
        for (int j = 0; j < 8; j++) {
            int c = 8 * j + 2 * lq;
            if (nodeA < n)
                *(float2*)&cout[(size_t)nodeA * 64 + c] =
                    make_float2(fmaxf(acc[j][0], 0.f), fmaxf(acc[j][1], 0.f));
            if (nodeB < n)
                *(float2*)&cout[(size_t)nodeB * 64 + c] =
                    make_float2(fmaxf(acc[j][2], 0.f), fmaxf(acc[j][3], 0.f));
        }
    } else {
        float dv0 = 0.f, dv1 = 0.f;
#pragma unroll
        for (int j = 0; j < 8; j++) {
            int c = 8 * j + 2 * lq;
            float w0 = Wrs[c], w1 = Wrs[c + 1];
            dv0 += fmaxf(acc[j][0], 0.f) * w0 + fmaxf(acc[j][1], 0.f) * w1;
            dv1 += fmaxf(acc[j][2], 0.f) * w0 + fmaxf(acc[j][3], 0.f) * w1;
        }
        dv0 += __shfl_xor_sync(0xffffffffu, dv0, 1);
        dv0 += __shfl_xor_sync(0xffffffffu, dv0, 2);
        dv1 += __shfl_xor_sync(0xffffffffu, dv1, 1);
        dv1 += __shfl_xor_sync(0xffffffffu, dv1, 2);
        if (lq == 0) {
            if (node0 + r0 < n)     out[node0 + r0]     = dv0;
            if (node0 + r0 + 8 < n) out[node0 + r0 + 8] = dv1;
        }
        __syncthreads();
#pragma unroll
        for (int j = 0; j < 8; j++) {
            int c = 8 * j + 2 * lq;
            *(float2*)&msgbuf[r0 * MSGP + c] =
                make_float2(fmaxf(acc[j][0], 0.f), fmaxf(acc[j][1], 0.f));
            *(float2*)&msgbuf[(r0 + 8) * MSGP + c] =
                make_float2(fmaxf(acc[j][2], 0.f), fmaxf(acc[j][3], 0.f));
        }
        __syncthreads();
        if (tid < 64) {
            int c = tid;
            float acc2 = 0.f, cnt = 0.f;
            int curb = -1;
            for (int i = 0; i < 128; i++) {
                int nd = node0 + i;
                if (nd >= n) break;
                int b = __ldg(&batch[nd]);
                if (b != curb) {
                    if (curb >= 0) {
                        atomicAdd(&g_means[curb * 64 + c], acc2);
                        if (c == 0) atomicAdd(&g_cnt[curb], cnt);
                    }
                    acc2 = 0.f; cnt = 0.f; curb = b;
                }
                acc2 += msgbuf[i * MSGP + c];
                cnt += 1.f;
            }
            if (curb >= 0) {
                atomicAdd(&g_means[curb * 64 + c], acc2);
                if (c == 0) atomicAdd(&g_cnt[curb], cnt);
            }
        }
    }
}

// ------------------------- FFMA2 GEMM (edge embedding) ---------------------
template <int K, int PITCH>
__device__ __forceinline__ void gemm_core8x8(const float* __restrict__ ins,
                                             const float* __restrict__ Ws,
                                             ull acc[8][4]) {
    int q  = threadIdx.x & 7;
    int rr = threadIdx.x >> 3;
#pragma unroll
    for (int j = 0; j < 8; j++)
#pragma unroll
        for (int m = 0; m < 4; m++) acc[j][m] = 0ull;

#pragma unroll 1
    for (int k = 0; k < K; k += 4) {
        float4 a[8];
#pragma unroll
        for (int j = 0; j < 8; j++)
            a[j] = *(const float4*)&ins[(rr + 16 * j) * PITCH + k];
#pragma unroll
        for (int kk = 0; kk < 4; kk++) {
            ulonglong2 w = *(const ulonglong2*)&Ws[(k + kk) * 64 + q * 8];
            ulonglong2 w2 = *(const ulonglong2*)&Ws[(k + kk) * 64 + q * 8 + 4];
#pragma unroll
            for (int j = 0; j < 8; j++) {
                float av = (kk == 0) ? a[j].x : (kk == 1) ? a[j].y
                         : (kk == 2) ? a[j].z : a[j].w;
                ull p;
                asm("mov.b64 %0, {%1, %1};" : "=l"(p) : "f"(av));
                asm("fma.rn.f32x2 %0, %1, %2, %0;" : "+l"(acc[j][0]) : "l"(p), "l"(w.x));
                asm("fma.rn.f32x2 %0, %1, %2, %0;" : "+l"(acc[j][1]) : "l"(p), "l"(w.y));
                asm("fma.rn.f32x2 %0, %1, %2, %0;" : "+l"(acc[j][2]) : "l"(p), "l"(w2.x));
                asm("fma.rn.f32x2 %0, %1, %2, %0;" : "+l"(acc[j][3]) : "l"(p), "l"(w2.y));
            }
        }
    }
}

__device__ __forceinline__ float4 acc_relu4(ull a0, ull a1) {
    float lo0, hi0, lo1, hi1;
    asm("mov.b64 {%0, %1}, %2;" : "=f"(lo0), "=f"(hi0) : "l"(a0));
    asm("mov.b64 {%0, %1}, %2;" : "=f"(lo1), "=f"(hi1) : "l"(a1));
    float4 o;
    o.x = fmaxf(lo0, 0.f); o.y = fmaxf(hi0, 0.f);
    o.z = fmaxf(lo1, 0.f); o.w = fmaxf(hi1, 0.f);
    return o;
}

// eemb = relu( naggH @ We2 ), K=64; staging patches col 63 = deg/degmax
__global__ __launch_bounds__(128) void k_gemm64(const float* __restrict__ A,
                                                const float* __restrict__ W,
                                                float* __restrict__ C, int n) {
    extern __shared__ float sm[];
    const int PITCH = 68;
    float* Ws  = sm;
    float* ins = sm + 64 * 64;
    int tid = threadIdx.x;
    int node0 = blockIdx.x * 128;
    float dmx = (float)max(g_degmax, 1);

    for (int idx = tid; idx < 64 * 16; idx += 128)
        ((float4*)Ws)[idx] = __ldg((const float4*)W + idx);
    for (int idx = tid; idx < 2048; idx += 128) {
        int r = idx >> 4, c4 = (idx & 15) << 2;
        int node = node0 + r;
        float4 va = make_float4(0.f, 0.f, 0.f, 0.f);
        if (node < n) {
            va = __ldg((const float4*)&A[(size_t)node * 64 + c4]);
            if (c4 == 60) va.w = (float)g_deg[node] / dmx;
        }
        *(float4*)&ins[r * PITCH + c4] = va;
    }
    __syncthreads();

    ull acc[8][4];
    gemm_core8x8<64, PITCH>(ins, Ws, acc);

    int q  = tid & 7;
    int rr = tid >> 3;
#pragma unroll
    for (int j = 0; j < 8; j++) {
        int node = node0 + rr + 16 * j;
        if (node < n) {
            float* Cr = &C[(size_t)node * 64 + q * 8];
            *(float4*)&Cr[0] = acc_relu4(acc[j][0], acc[j][1]);
            *(float4*)&Cr[4] = acc_relu4(acc[j][2], acc[j][3]);
        }
    }
}

// ------------------------------- readout -----------------------------------
__global__ void k_gconst(const float* __restrict__ Wp, const float* __restrict__ Wr,
                         const float* __restrict__ br) {
    int g = blockIdx.x;
    int t = threadIdx.x;
    __shared__ float m[64];
    __shared__ float red[64];
    float cnt = g_cnt[g];
    if (cnt <= 0.f) { if (t == 0) g_gconst[g] = 0.f; return; }
    m[t] = g_means[g * 64 + t] / cnt;
    __syncthreads();
    float p = 0.f;
#pragma unroll 8
    for (int k = 0; k < 64; k++) p += m[k] * __ldg(&Wp[k * 64 + t]);
    red[t] = fmaxf(p, 0.f) * __ldg(&Wr[t]);
    __syncthreads();
    if (t < 32) {
        float s = red[t] + red[t + 32];
#pragma unroll
        for (int off = 16; off > 0; off >>= 1) s += __shfl_down_sync(0xffffffffu, s, off);
        if (t == 0) g_gconst[g] = s + __ldg(&br[0]);
    }
}

__global__ void k_addg(const int* __restrict__ batch, float* __restrict__ out, int n) {
    int i = blockIdx.x * blockDim.x + threadIdx.x;
    if (i < n) out[i] += g_gconst[__ldg(&batch[i])];
}

// ---------------------------------------------------------------------------
extern "C" void kernel_launch(void* const* d_in, const int* in_sizes, int n_in,
                              void* d_out, int out_size) {
    const float* x    = (const float*)d_in[0];
    const float* Wi   = (const float*)d_in[1];
    const float* We1  = (const float*)d_in[2];
    const float* We2  = (const float*)d_in[3];
    const float* Wmsg = (const float*)d_in[4];
    const float* Wupd = (const float*)d_in[5];
    const float* Wp   = (const float*)d_in[6];
    const float* Wr   = (const float*)d_in[7];
    const float* br   = (const float*)d_in[8];
    const int*   eidx = (const int*)d_in[9];
    const int*   batch= (const int*)d_in[10];

    int n    = in_sizes[10];
    int E    = in_sizes[9] / 2;
    int nobs = in_sizes[0] / n;
    int L    = in_sizes[4] / (128 * 64);
    const int* row = eidx;
    const int* col = eidx + E;
    float* out = (float*)d_out;

    float *curA, *curB, *hbuf, *nagg, *naggH, *eemb, *means, *cnt;
    int *deg, *degmax;
    cudaGetSymbolAddress((void**)&curA, g_curA);
    cudaGetSymbolAddress((void**)&curB, g_curB);
    cudaGetSymbolAddress((void**)&hbuf, g_h);
    cudaGetSymbolAddress((void**)&nagg, g_nagg);
    cudaGetSymbolAddress((void**)&naggH, g_naggH);
    cudaGetSymbolAddress((void**)&eemb, g_eemb);
    cudaGetSymbolAddress((void**)&means, g_means);
    cudaGetSymbolAddress((void**)&cnt,   g_cnt);
    cudaGetSymbolAddress((void**)&deg,   g_deg);
    cudaGetSymbolAddress((void**)&degmax, g_degmax);

    const int SMEM_MMA = (10240 + 128 * 68) * 4;  // Bf 40KB + msgbuf 34KB = 75776
    const int SMEM64   = (64 * 64 + 128 * 68) * 4;
    cudaFuncSetAttribute(k_layer_mma<false>, cudaFuncAttributeMaxDynamicSharedMemorySize, SMEM_MMA);
    cudaFuncSetAttribute(k_layer_mma<true>,  cudaFuncAttributeMaxDynamicSharedMemorySize, SMEM_MMA);
    cudaFuncSetAttribute(k_layer_mma<false>, cudaFuncAttributePreferredSharedMemoryCarveout, 100);
    cudaFuncSetAttribute(k_layer_mma<true>,  cudaFuncAttributePreferredSharedMemoryCarveout, 100);
    cudaFuncSetAttribute(k_gemm64, cudaFuncAttributeMaxDynamicSharedMemorySize, SMEM64);

    int gFI = (E + n * 64 + 255) / 256;
    int gHW = (n * 16 + 255) / 256;
    int gG  = (n + 127) / 128;
    int gA  = (n + 255) / 256;

    cudaMemsetAsync(deg,    0, (size_t)n * sizeof(int));
    cudaMemsetAsync(degmax, 0, sizeof(int));
    cudaMemsetAsync(means,  0, (size_t)MAXG * FD * sizeof(float));
    cudaMemsetAsync(cnt,    0, (size_t)MAXG * sizeof(float));

    k_fillpad<<<gFI, 256>>>(row, col, x, Wi, We1, E, n, nobs);   // kernel 1
    k_dgather<<<gHW, 256>>>(hbuf, curA, naggH, nagg, n);         // kernel 2
    k_gemm64<<<gG, 128, SMEM64>>>(naggH, We2, eemb, n);          // kernel 3

    float* cin = curA;
    float* cout = curB;
    for (int l = 0; l < L; l++) {
        bool last = (l == L - 1);
        if (l > 0) k_gather<<<gHW, 256>>>(cin, nagg, n);
        if (!last) {
            k_layer_mma<false><<<gG, 256, SMEM_MMA>>>(nagg, eemb, cin,   // kernel 4 (l=0): profiled
                                                      Wmsg + (size_t)l * 8192,
                                                      Wupd + (size_t)l * 8192,
                                                      cout, nullptr, nullptr, nullptr, n);
            float* tmp = cin; cin = cout; cout = tmp;
        } else {
            k_layer_mma<true><<<gG, 256, SMEM_MMA>>>(nagg, eemb, cin,
                                                     Wmsg + (size_t)l * 8192,
                                                     Wupd + (size_t)l * 8192,
                                                     nullptr, Wr, batch, out, n);
        }
    }

    k_gconst<<<MAXG, 64>>>(Wp, Wr, br);
    k_addg<<<gA, 256>>>(batch, out, n);
}